// round 2
// baseline (speedup 1.0000x reference)
#include <cuda_runtime.h>
#include <math.h>

// Problem constants
#define NTOK 4096      // B*S
#define DMODEL 512
#define NEXP 8
#define TOPK 2
#define HDIM 2048
#define EHDIM (NEXP * HDIM)   // 16384

// ---------------- device scratch (no allocations allowed) ----------------
__device__ float  g_combined[NTOK * HDIM];        // 33.5 MB accumulator
__device__ int    g_cnt[NEXP];
__device__ double g_esum[NEXP];                   // fp64 for lb-loss accuracy
__device__ int    g_elist[NEXP * NTOK];
__device__ float  g_eprob[NEXP * NTOK];

// ---------------- zero kernels ----------------
__global__ void zero_small_kernel() {
    int t = threadIdx.x;
    if (t < NEXP) { g_cnt[t] = 0; g_esum[t] = 0.0; }
}

__global__ void zero_combined_kernel() {
    // grid-stride float4 zero over NTOK*HDIM floats
    float4* p = reinterpret_cast<float4*>(g_combined);
    const int total4 = (NTOK * HDIM) / 4;  // 2,097,152
    for (int i = blockIdx.x * blockDim.x + threadIdx.x; i < total4;
         i += gridDim.x * blockDim.x) {
        p[i] = make_float4(0.f, 0.f, 0.f, 0.f);
    }
}

// ---------------- router: one warp per token ----------------
__global__ void router_kernel(const float* __restrict__ x,
                              const float* __restrict__ w_router) {
    int warp = (blockIdx.x * blockDim.x + threadIdx.x) >> 5;
    int lane = threadIdx.x & 31;
    if (warp >= NTOK) return;
    int n = warp;

    float acc[NEXP];
#pragma unroll
    for (int e = 0; e < NEXP; e++) acc[e] = 0.f;

    const float* xr = x + (long)n * DMODEL;
    for (int d = lane; d < DMODEL; d += 32) {
        float xv = xr[d];
        const float* w = w_router + d * NEXP;
#pragma unroll
        for (int e = 0; e < NEXP; e++) acc[e] += xv * w[e];
    }
#pragma unroll
    for (int off = 16; off > 0; off >>= 1) {
#pragma unroll
        for (int e = 0; e < NEXP; e++)
            acc[e] += __shfl_xor_sync(0xFFFFFFFFu, acc[e], off);
    }

    if (lane == 0) {
        // softmax over 8 experts
        float mx = acc[0];
#pragma unroll
        for (int e = 1; e < NEXP; e++) mx = fmaxf(mx, acc[e]);
        float s = 0.f;
        float probs[NEXP];
#pragma unroll
        for (int e = 0; e < NEXP; e++) { probs[e] = expf(acc[e] - mx); s += probs[e]; }
        float inv = 1.f / s;
#pragma unroll
        for (int e = 0; e < NEXP; e++) {
            probs[e] *= inv;
            atomicAdd(&g_esum[e], (double)probs[e]);   // fp64 accumulation
        }
        // top-2 (lower index wins ties, matching jax.lax.top_k)
        int i1 = 0;
#pragma unroll
        for (int e = 1; e < NEXP; e++) if (probs[e] > probs[i1]) i1 = e;
        int i2 = (i1 == 0) ? 1 : 0;
#pragma unroll
        for (int e = 0; e < NEXP; e++)
            if (e != i1 && probs[e] > probs[i2]) i2 = e;

        float p1 = probs[i1], p2 = probs[i2];
        float rn = 1.f / (p1 + p2 + 1e-10f);
        int pos1 = atomicAdd(&g_cnt[i1], 1);
        g_elist[i1 * NTOK + pos1] = n;
        g_eprob[i1 * NTOK + pos1] = p1 * rn;
        int pos2 = atomicAdd(&g_cnt[i2], 1);
        g_elist[i2 * NTOK + pos2] = n;
        g_eprob[i2 * NTOK + pos2] = p2 * rn;
    }
}

// ---------------- gate/up gather-GEMM + combine ----------------
// grid: (HDIM/64, NTOK/64, NEXP); block: (16,16)
// Each block: 64 tokens (gathered from expert list) x 64 h-cols, dual acc (gate,up)
__global__ __launch_bounds__(256) void gateup_kernel(
    const float* __restrict__ x,
    const float* __restrict__ w_gate,
    const float* __restrict__ w_up) {
    const int TK = 16;
    __shared__ __align__(16) float Xs[TK][68];   // transposed X tile, padded
    __shared__ __align__(16) float Gs[TK][64];
    __shared__ __align__(16) float Us[TK][64];
    __shared__ int   sTok[64];
    __shared__ float sP[64];

    const int e = blockIdx.z;
    const int cnt = g_cnt[e];
    const int row0 = blockIdx.y * 64;
    if (row0 >= cnt) return;
    const int h0 = blockIdx.x * 64;
    const int tx = threadIdx.x, ty = threadIdx.y;
    const int tid = ty * 16 + tx;

    if (tid < 64) {
        int r = row0 + tid;
        if (r < cnt) { sTok[tid] = g_elist[e * NTOK + r]; sP[tid] = g_eprob[e * NTOK + r]; }
        else         { sTok[tid] = -1;                     sP[tid] = 0.f; }
    }
    __syncthreads();

    float accG[4][4], accU[4][4];
#pragma unroll
    for (int i = 0; i < 4; i++)
#pragma unroll
        for (int j = 0; j < 4; j++) { accG[i][j] = 0.f; accU[i][j] = 0.f; }

    const float* wg = w_gate + e * HDIM + h0;
    const float* wu = w_up   + e * HDIM + h0;

    for (int d0 = 0; d0 < DMODEL; d0 += TK) {
        // X gather: 64 rows x 16 d, transposed into Xs[kk][r]
#pragma unroll
        for (int it = 0; it < 4; it++) {
            int idx = tid + it * 256;
            int kk = idx & 15, r = idx >> 4;
            int t = sTok[r];
            Xs[kk][r] = (t >= 0) ? x[t * DMODEL + d0 + kk] : 0.f;
        }
        // W tiles: 16 x 64 each (coalesced along h)
#pragma unroll
        for (int it = 0; it < 4; it++) {
            int idx = tid + it * 256;
            int c = idx & 63, kk = idx >> 6;
            int off = (d0 + kk) * EHDIM + c;
            Gs[kk][c] = wg[off];
            Us[kk][c] = wu[off];
        }
        __syncthreads();
#pragma unroll
        for (int kk = 0; kk < TK; kk++) {
            float4 xv = *reinterpret_cast<const float4*>(&Xs[kk][ty * 4]);
            float4 gv = *reinterpret_cast<const float4*>(&Gs[kk][tx * 4]);
            float4 uv = *reinterpret_cast<const float4*>(&Us[kk][tx * 4]);
            float xa[4] = {xv.x, xv.y, xv.z, xv.w};
            float ga[4] = {gv.x, gv.y, gv.z, gv.w};
            float ua[4] = {uv.x, uv.y, uv.z, uv.w};
#pragma unroll
            for (int i = 0; i < 4; i++)
#pragma unroll
                for (int j = 0; j < 4; j++) {
                    accG[i][j] += xa[i] * ga[j];
                    accU[i][j] += xa[i] * ua[j];
                }
        }
        __syncthreads();
    }

    // epilogue: p * silu(g) * u, atomic-accumulate into combined
#pragma unroll
    for (int i = 0; i < 4; i++) {
        int r = ty * 4 + i;
        int t = sTok[r];
        if (t < 0) continue;
        float p = sP[r];
#pragma unroll
        for (int j = 0; j < 4; j++) {
            float g = accG[i][j];
            float u = accU[i][j];
            float val = p * (g / (1.f + expf(-g))) * u;
            atomicAdd(&g_combined[t * HDIM + h0 + tx * 4 + j], val);
        }
    }
}

// ---------------- down projection GEMM ----------------
// combined[NTOK, HDIM] @ w_down[HDIM, DMODEL] -> out[NTOK, DMODEL]
// grid: (DMODEL/64, NTOK/64); block (16,16)
__global__ __launch_bounds__(256) void down_kernel(
    const float* __restrict__ w_down,
    float* __restrict__ out) {
    const int TK = 16;
    __shared__ __align__(16) float As[TK][68];
    __shared__ __align__(16) float Bs[TK][64];

    const int row0 = blockIdx.y * 64;
    const int c0 = blockIdx.x * 64;
    const int tx = threadIdx.x, ty = threadIdx.y;
    const int tid = ty * 16 + tx;

    float acc[4][4];
#pragma unroll
    for (int i = 0; i < 4; i++)
#pragma unroll
        for (int j = 0; j < 4; j++) acc[i][j] = 0.f;

    for (int d0 = 0; d0 < HDIM; d0 += TK) {
#pragma unroll
        for (int it = 0; it < 4; it++) {
            int idx = tid + it * 256;
            int kk = idx & 15, r = idx >> 4;
            As[kk][r] = g_combined[(row0 + r) * HDIM + d0 + kk];
        }
#pragma unroll
        for (int it = 0; it < 4; it++) {
            int idx = tid + it * 256;
            int c = idx & 63, kk = idx >> 6;
            Bs[kk][c] = w_down[(d0 + kk) * DMODEL + c0 + c];
        }
        __syncthreads();
#pragma unroll
        for (int kk = 0; kk < TK; kk++) {
            float4 av = *reinterpret_cast<const float4*>(&As[kk][ty * 4]);
            float4 bv = *reinterpret_cast<const float4*>(&Bs[kk][tx * 4]);
            float aa[4] = {av.x, av.y, av.z, av.w};
            float bb[4] = {bv.x, bv.y, bv.z, bv.w};
#pragma unroll
            for (int i = 0; i < 4; i++)
#pragma unroll
                for (int j = 0; j < 4; j++) acc[i][j] += aa[i] * bb[j];
        }
        __syncthreads();
    }

#pragma unroll
    for (int i = 0; i < 4; i++) {
        int r = row0 + ty * 4 + i;
#pragma unroll
        for (int j = 0; j < 4; j++) {
            out[r * DMODEL + c0 + tx * 4 + j] = acc[i][j];
        }
    }
}

// ---------------- load-balancing loss (fp64 path) ----------------
__global__ void lbloss_kernel(float* __restrict__ out_scalar) {
    if (threadIdx.x == 0 && blockIdx.x == 0) {
        double lb = 0.0;
#pragma unroll
        for (int e = 0; e < NEXP; e++) {
            double m = g_esum[e] / (double)NTOK;
            lb += m * log(m * (double)NEXP + 1e-10);
        }
        out_scalar[0] = (float)((double)NEXP * lb);
    }
}

// ---------------- launch ----------------
extern "C" void kernel_launch(void* const* d_in, const int* in_sizes, int n_in,
                              void* d_out, int out_size) {
    const float* x        = (const float*)d_in[0];
    const float* w_router = (const float*)d_in[1];
    const float* w_gate   = (const float*)d_in[2];
    const float* w_up     = (const float*)d_in[3];
    const float* w_down   = (const float*)d_in[4];
    float* out = (float*)d_out;

    zero_small_kernel<<<1, 32>>>();
    zero_combined_kernel<<<4096, 256>>>();

    // router: 8 warps/block -> 512 blocks
    router_kernel<<<NTOK / 8, 256>>>(x, w_router);

    dim3 blk(16, 16);
    dim3 grdGU(HDIM / 64, NTOK / 64, NEXP);
    gateup_kernel<<<grdGU, blk>>>(x, w_gate, w_up);

    dim3 grdD(DMODEL / 64, NTOK / 64);
    down_kernel<<<grdD, blk>>>(w_down, out);

    lbloss_kernel<<<1, 32>>>(out + (out_size - 1));
}

// round 5
// speedup vs baseline: 2.2073x; 2.2073x over previous
#include <cuda_runtime.h>
#include <cuda_bf16.h>
#include <math.h>
#include <stdint.h>

#define NTOK 4096
#define DMODEL 512
#define NEXP 8
#define HDIM 2048
#define EHDIM (NEXP * HDIM)   // 16384

// ---------------- device scratch ----------------
__device__ __align__(16) unsigned short g_xh[NTOK * DMODEL];
__device__ __align__(16) unsigned short g_xl[NTOK * DMODEL];
__device__ __align__(16) unsigned short g_wgh[EHDIM * DMODEL];
__device__ __align__(16) unsigned short g_wgl[EHDIM * DMODEL];
__device__ __align__(16) unsigned short g_wuh[EHDIM * DMODEL];
__device__ __align__(16) unsigned short g_wul[EHDIM * DMODEL];
__device__ __align__(16) unsigned short g_wdh[DMODEL * HDIM];
__device__ __align__(16) unsigned short g_wdl[DMODEL * HDIM];
__device__ __align__(16) float  g_part[2 * NTOK * HDIM];
__device__ int    g_cnt[NEXP];
__device__ double g_esum[NEXP];
__device__ int    g_elist[NEXP * NTOK];   // token | (slot<<16)
__device__ float  g_eprob[NEXP * NTOK];

// ---------------- helpers ----------------
__device__ __forceinline__ uint32_t smem_u32(const void* p) {
    uint32_t a;
    asm("{ .reg .u64 t; cvta.to.shared.u64 t, %1; cvt.u32.u64 %0, t; }"
        : "=r"(a) : "l"(p));
    return a;
}
__device__ __forceinline__ void cp16(uint32_t dst, const void* src) {
    asm volatile("cp.async.cg.shared.global [%0], [%1], 16;" :: "r"(dst), "l"(src));
}
#define CP_COMMIT() asm volatile("cp.async.commit_group;" ::: "memory")
#define CP_WAIT1()  asm volatile("cp.async.wait_group 1;" ::: "memory")
#define CP_WAIT0()  asm volatile("cp.async.wait_group 0;" ::: "memory")

// m16n8k16 bf16 MMA (sm_80 baseline PTX -> tensor pipe)
__device__ __forceinline__ void mma16(float* c, const uint32_t* a, const uint32_t* b) {
    asm volatile(
        "mma.sync.aligned.m16n8k16.row.col.f32.bf16.bf16.f32 "
        "{%0,%1,%2,%3}, {%4,%5,%6,%7}, {%8,%9}, {%0,%1,%2,%3};"
        : "+f"(c[0]), "+f"(c[1]), "+f"(c[2]), "+f"(c[3])
        : "r"(a[0]), "r"(a[1]), "r"(a[2]), "r"(a[3]), "r"(b[0]), "r"(b[1]));
}

__device__ __forceinline__ void bsplit(float v, unsigned short& h, unsigned short& l) {
    __nv_bfloat16 hb = __float2bfloat16(v);
    h = __bfloat16_as_ushort(hb);
    float r = v - __bfloat162float(hb);
    l = __bfloat16_as_ushort(__float2bfloat16(r));
}
__device__ __forceinline__ uint32_t pack2(unsigned short a, unsigned short b) {
    return (uint32_t)a | ((uint32_t)b << 16);
}

// ---------------- prep kernels ----------------
__global__ void zero_small_kernel() {
    int t = threadIdx.x;
    if (t < NEXP) { g_cnt[t] = 0; g_esum[t] = 0.0; }
}

__global__ void prep_xc(const float* __restrict__ x) {
    int i = blockIdx.x * blockDim.x + threadIdx.x;   // over NTOK*DMODEL/4
    float4 v = reinterpret_cast<const float4*>(x)[i];
    unsigned short h0, h1, h2, h3, l0, l1, l2, l3;
    bsplit(v.x, h0, l0); bsplit(v.y, h1, l1);
    bsplit(v.z, h2, l2); bsplit(v.w, h3, l3);
    ushort4 hv = make_ushort4(h0, h1, h2, h3);
    ushort4 lv = make_ushort4(l0, l1, l2, l3);
    reinterpret_cast<ushort4*>(g_xh)[i] = hv;
    reinterpret_cast<ushort4*>(g_xl)[i] = lv;
}

__global__ void prep_wgu(const float* __restrict__ wg, const float* __restrict__ wu) {
    __shared__ float tg[32][33], tu[32][33];
    int hb = blockIdx.x * 32, db = blockIdx.y * 32;
    int tx = threadIdx.x, ty = threadIdx.y;   // (32, 8)
#pragma unroll
    for (int i = 0; i < 4; i++) {
        int d = db + ty + i * 8;
        tg[ty + i * 8][tx] = wg[(size_t)d * EHDIM + hb + tx];
        tu[ty + i * 8][tx] = wu[(size_t)d * EHDIM + hb + tx];
    }
    __syncthreads();
#pragma unroll
    for (int i = 0; i < 4; i++) {
        int h = hb + ty + i * 8;
        size_t o = (size_t)h * DMODEL + db + tx;
        unsigned short hh, ll;
        bsplit(tg[tx][ty + i * 8], hh, ll);
        g_wgh[o] = hh; g_wgl[o] = ll;
        bsplit(tu[tx][ty + i * 8], hh, ll);
        g_wuh[o] = hh; g_wul[o] = ll;
    }
}

__global__ void prep_wd(const float* __restrict__ wd) {
    __shared__ float t[32][33];
    int db = blockIdx.x * 32, hb = blockIdx.y * 32;
    int tx = threadIdx.x, ty = threadIdx.y;
#pragma unroll
    for (int i = 0; i < 4; i++) {
        t[ty + i * 8][tx] = wd[(size_t)(hb + ty + i * 8) * DMODEL + db + tx];
    }
    __syncthreads();
#pragma unroll
    for (int i = 0; i < 4; i++) {
        size_t o = (size_t)(db + ty + i * 8) * HDIM + hb + tx;
        unsigned short hh, ll;
        bsplit(t[tx][ty + i * 8], hh, ll);
        g_wdh[o] = hh; g_wdl[o] = ll;
    }
}

// ---------------- router: one warp per token ----------------
__global__ void router_kernel(const float* __restrict__ x,
                              const float* __restrict__ w_router) {
    int warp = (blockIdx.x * blockDim.x + threadIdx.x) >> 5;
    int lane = threadIdx.x & 31;
    if (warp >= NTOK) return;
    int n = warp;

    float acc[NEXP];
#pragma unroll
    for (int e = 0; e < NEXP; e++) acc[e] = 0.f;
    const float* xr = x + (size_t)n * DMODEL;
    for (int d = lane; d < DMODEL; d += 32) {
        float xv = xr[d];
        const float* w = w_router + d * NEXP;
#pragma unroll
        for (int e = 0; e < NEXP; e++) acc[e] += xv * w[e];
    }
#pragma unroll
    for (int off = 16; off > 0; off >>= 1)
#pragma unroll
        for (int e = 0; e < NEXP; e++)
            acc[e] += __shfl_xor_sync(0xFFFFFFFFu, acc[e], off);

    if (lane == 0) {
        float mx = acc[0];
#pragma unroll
        for (int e = 1; e < NEXP; e++) mx = fmaxf(mx, acc[e]);
        float s = 0.f, probs[NEXP];
#pragma unroll
        for (int e = 0; e < NEXP; e++) { probs[e] = expf(acc[e] - mx); s += probs[e]; }
        float inv = 1.f / s;
#pragma unroll
        for (int e = 0; e < NEXP; e++) {
            probs[e] *= inv;
            atomicAdd(&g_esum[e], (double)probs[e]);
        }
        int i1 = 0;
#pragma unroll
        for (int e = 1; e < NEXP; e++) if (probs[e] > probs[i1]) i1 = e;
        int i2 = (i1 == 0) ? 1 : 0;
#pragma unroll
        for (int e = 0; e < NEXP; e++)
            if (e != i1 && probs[e] > probs[i2]) i2 = e;

        float p1 = probs[i1], p2 = probs[i2];
        float rn = 1.f / (p1 + p2 + 1e-10f);
        int pos1 = atomicAdd(&g_cnt[i1], 1);
        g_elist[i1 * NTOK + pos1] = n;                // slot 0
        g_eprob[i1 * NTOK + pos1] = p1 * rn;
        int pos2 = atomicAdd(&g_cnt[i2], 1);
        g_elist[i2 * NTOK + pos2] = n | (1 << 16);    // slot 1
        g_eprob[i2 * NTOK + pos2] = p2 * rn;
    }
}

// ---------------- gate/up split-bf16 warp-MMA GEMM ----------------
// BM=128 tokens, BN=64 h (dual: G and U), K chunks of 16.
// smem row = [hi 8 words | lo 8 words | pad 4] stride 20 words (80B).
#define RS 20

__global__ __launch_bounds__(256) void gateup_mma() {
    __shared__ __align__(16) uint32_t Xs[2][128 * RS];
    __shared__ __align__(16) uint32_t Gs[2][64 * RS];
    __shared__ __align__(16) uint32_t Us[2][64 * RS];
    __shared__ float  sP[128];
    __shared__ float* sDst[128];

    const int tid = threadIdx.x;
    const int e = blockIdx.z;
    const int cnt = g_cnt[e];
    const int row0 = blockIdx.x * 128;
    if (row0 >= cnt) return;
    const int h0 = blockIdx.y * 64;

    if (tid < 128) {
        int gr = row0 + tid;
        bool valid = gr < cnt;
        int ent = valid ? g_elist[e * NTOK + gr] : 0;
        int t = ent & 0xFFFF;
        int slot = (ent >> 16) & 1;
        sP[tid] = valid ? g_eprob[e * NTOK + gr] : 0.f;
        sDst[tid] = valid ? (g_part + ((size_t)slot * NTOK + t) * HDIM + h0) : (float*)0;
    }

    // cp.async setup. q decodes (hilo, seg): 16B seg s of hi/lo row half.
    const int q = tid & 3, hilo = q >> 1, seg = q & 1;

    // X: 128 rows x 4 ops = 512 -> 2 per thread
    const unsigned short* xsrc[2];
    uint32_t xdst[2][2];
#pragma unroll
    for (int i = 0; i < 2; i++) {
        int r = (tid >> 2) + i * 64;
        int gr = row0 + r;
        int ent = (gr < cnt) ? g_elist[e * NTOK + gr] : 0;
        int t = ent & 0xFFFF;
        xsrc[i] = (hilo ? g_xl : g_xh) + (size_t)t * DMODEL + seg * 8;
        xdst[i][0] = smem_u32(&Xs[0][r * RS]) + hilo * 32 + seg * 16;
        xdst[i][1] = smem_u32(&Xs[1][r * RS]) + hilo * 32 + seg * 16;
    }
    // G/U: 64 rows x 4 ops = 256 each -> 1 per thread per array
    int wrow = tid >> 2;   // 0..63
    size_t wro = (size_t)(e * HDIM + h0 + wrow) * DMODEL + seg * 8;
    const unsigned short* gsrc = (hilo ? g_wgl : g_wgh) + wro;
    const unsigned short* usrc = (hilo ? g_wul : g_wuh) + wro;
    uint32_t gdst[2], udst[2];
#pragma unroll
    for (int b = 0; b < 2; b++) {
        gdst[b] = smem_u32(&Gs[b][wrow * RS]) + hilo * 32 + seg * 16;
        udst[b] = smem_u32(&Us[b][wrow * RS]) + hilo * 32 + seg * 16;
    }

    const int warp = tid >> 5, lane = tid & 31;
    const int wm = warp & 3, wn = warp >> 2;
    const int grp = lane >> 2, tig = lane & 3;

    float accG[2][4][4], accU[2][4][4];
#pragma unroll
    for (int mt = 0; mt < 2; mt++)
#pragma unroll
        for (int nt = 0; nt < 4; nt++)
#pragma unroll
            for (int k = 0; k < 4; k++) { accG[mt][nt][k] = 0.f; accU[mt][nt][k] = 0.f; }

    // prologue: chunks 0,1  (chunk = 16 K-elems = 32B per row-half)
#pragma unroll
    for (int c = 0; c < 2; c++) {
        cp16(xdst[0][c], xsrc[0] + c * 16);
        cp16(xdst[1][c], xsrc[1] + c * 16);
        cp16(gdst[c], gsrc + c * 16);
        cp16(udst[c], usrc + c * 16);
        CP_COMMIT();
    }

    const int NCH = DMODEL / 16;   // 32
    for (int c = 0; c < NCH; c++) {
        int buf = c & 1;
        if (c + 1 < NCH) CP_WAIT1(); else CP_WAIT0();
        __syncthreads();

        const uint32_t* xb = Xs[buf];
        const uint32_t* gb = Gs[buf];
        const uint32_t* ub = Us[buf];

        uint32_t ah[2][4], al[2][4];
#pragma unroll
        for (int mt = 0; mt < 2; mt++) {
            int r = wm * 32 + mt * 16 + grp;
            int b0 = r * RS, b1 = (r + 8) * RS;
            ah[mt][0] = xb[b0 + tig];     ah[mt][1] = xb[b1 + tig];
            ah[mt][2] = xb[b0 + tig + 4]; ah[mt][3] = xb[b1 + tig + 4];
            al[mt][0] = xb[b0 + 8 + tig];     al[mt][1] = xb[b1 + 8 + tig];
            al[mt][2] = xb[b0 + 8 + tig + 4]; al[mt][3] = xb[b1 + 8 + tig + 4];
        }
        uint32_t gh[4][2], gl[4][2], uh[4][2], ul[4][2];
#pragma unroll
        for (int nt = 0; nt < 4; nt++) {
            int n = wn * 32 + nt * 8 + grp;
            int nb = n * RS;
            gh[nt][0] = gb[nb + tig]; gh[nt][1] = gb[nb + tig + 4];
            gl[nt][0] = gb[nb + 8 + tig]; gl[nt][1] = gb[nb + 8 + tig + 4];
            uh[nt][0] = ub[nb + tig]; uh[nt][1] = ub[nb + tig + 4];
            ul[nt][0] = ub[nb + 8 + tig]; ul[nt][1] = ub[nb + 8 + tig + 4];
        }
#pragma unroll
        for (int mt = 0; mt < 2; mt++)
#pragma unroll
            for (int nt = 0; nt < 4; nt++) {
                mma16(accG[mt][nt], ah[mt], gh[nt]);
                mma16(accG[mt][nt], ah[mt], gl[nt]);
                mma16(accG[mt][nt], al[mt], gh[nt]);
                mma16(accU[mt][nt], ah[mt], uh[nt]);
                mma16(accU[mt][nt], ah[mt], ul[nt]);
                mma16(accU[mt][nt], al[mt], uh[nt]);
            }
        __syncthreads();

        if (c + 2 < NCH) {
            int k0 = (c + 2) * 16;
            cp16(xdst[0][buf], xsrc[0] + k0);
            cp16(xdst[1][buf], xsrc[1] + k0);
            cp16(gdst[buf], gsrc + k0);
            cp16(udst[buf], usrc + k0);
            CP_COMMIT();
        }
    }

    // epilogue: p * silu(g) * u, one exact store per (token,slot,h)
#pragma unroll
    for (int mt = 0; mt < 2; mt++) {
        int r0 = wm * 32 + mt * 16 + grp;
        int r1 = r0 + 8;
        float p0 = sP[r0], p1 = sP[r1];
        float* d0 = sDst[r0];
        float* d1 = sDst[r1];
#pragma unroll
        for (int nt = 0; nt < 4; nt++) {
            int coff = wn * 32 + nt * 8 + tig * 2;
            if (d0) {
                float g0 = accG[mt][nt][0], u0 = accU[mt][nt][0];
                float g1 = accG[mt][nt][1], u1 = accU[mt][nt][1];
                float2 v;
                v.x = p0 * (g0 / (1.f + __expf(-g0))) * u0;
                v.y = p0 * (g1 / (1.f + __expf(-g1))) * u1;
                *reinterpret_cast<float2*>(d0 + coff) = v;
            }
            if (d1) {
                float g2 = accG[mt][nt][2], u2 = accU[mt][nt][2];
                float g3 = accG[mt][nt][3], u3 = accU[mt][nt][3];
                float2 v;
                v.x = p1 * (g2 / (1.f + __expf(-g2))) * u2;
                v.y = p1 * (g3 / (1.f + __expf(-g3))) * u3;
                *reinterpret_cast<float2*>(d1 + coff) = v;
            }
        }
    }
}

// ---------------- down split-bf16 warp-MMA GEMM ----------------
// BM=128, BN=64, K=2048 chunks of 16. A = part0+part1 split in regs.
__global__ __launch_bounds__(256) void down_mma(float* __restrict__ out) {
    __shared__ __align__(16) uint32_t As[2][128 * RS];
    __shared__ __align__(16) uint32_t Bs[2][64 * RS];

    const int tid = threadIdx.x;
    const int row0 = blockIdx.x * 128;
    const int c0 = blockIdx.y * 64;

    // A staging: 512 float4/chunk -> 2 per thread
    const float4* asrc0[2];
    const float4* asrc1[2];
    uint32_t adh[2][2], adl[2][2];
#pragma unroll
    for (int i = 0; i < 2; i++) {
        int idx = tid + i * 256;
        int r = idx >> 2, c4 = idx & 3;
        size_t off = (size_t)(row0 + r) * HDIM + c4 * 4;
        asrc0[i] = reinterpret_cast<const float4*>(g_part + off);
        asrc1[i] = reinterpret_cast<const float4*>(g_part + (size_t)NTOK * HDIM + off);
#pragma unroll
        for (int b = 0; b < 2; b++) {
            uint32_t base = smem_u32(&As[b][r * RS + c4 * 2]);
            adh[i][b] = base;
            adl[i][b] = base + 32;
        }
    }
    // B: 64 rows x 4 ops = 256 -> 1 per thread
    const int q = tid & 3, hilo = q >> 1, seg = q & 1;
    int wrow = tid >> 2;
    const unsigned short* bsrc =
        (hilo ? g_wdl : g_wdh) + (size_t)(c0 + wrow) * HDIM + seg * 8;
    uint32_t bdst[2];
#pragma unroll
    for (int b = 0; b < 2; b++)
        bdst[b] = smem_u32(&Bs[b][wrow * RS]) + hilo * 32 + seg * 16;

    const int warp = tid >> 5, lane = tid & 31;
    const int wm = warp & 3, wn = warp >> 2;
    const int grp = lane >> 2, tig = lane & 3;

    float acc[2][4][4];
#pragma unroll
    for (int mt = 0; mt < 2; mt++)
#pragma unroll
        for (int nt = 0; nt < 4; nt++)
#pragma unroll
            for (int k = 0; k < 4; k++) acc[mt][nt][k] = 0.f;

    float4 rA0[2], rA1[2];
#pragma unroll
    for (int i = 0; i < 2; i++) { rA0[i] = asrc0[i][0]; rA1[i] = asrc1[i][0]; }

#pragma unroll
    for (int c = 0; c < 2; c++) {
        cp16(bdst[c], bsrc + c * 16);
        CP_COMMIT();
    }

    const int NCH = HDIM / 16;   // 128
    for (int c = 0; c < NCH; c++) {
        int buf = c & 1;
        // store A chunk c: sum + bf16 hi/lo split
#pragma unroll
        for (int i = 0; i < 2; i++) {
            float s0 = rA0[i].x + rA1[i].x;
            float s1 = rA0[i].y + rA1[i].y;
            float s2 = rA0[i].z + rA1[i].z;
            float s3 = rA0[i].w + rA1[i].w;
            unsigned short h0, h1, h2, h3, l0, l1, l2, l3;
            bsplit(s0, h0, l0); bsplit(s1, h1, l1);
            bsplit(s2, h2, l2); bsplit(s3, h3, l3);
            uint32_t hw0 = pack2(h0, h1), hw1 = pack2(h2, h3);
            uint32_t lw0 = pack2(l0, l1), lw1 = pack2(l2, l3);
            asm volatile("st.shared.v2.b32 [%0], {%1,%2};"
                         :: "r"(adh[i][buf]), "r"(hw0), "r"(hw1) : "memory");
            asm volatile("st.shared.v2.b32 [%0], {%1,%2};"
                         :: "r"(adl[i][buf]), "r"(lw0), "r"(lw1) : "memory");
        }
        if (c + 1 < NCH) {
            int koff4 = (c + 1) * 4;
#pragma unroll
            for (int i = 0; i < 2; i++) { rA0[i] = asrc0[i][koff4]; rA1[i] = asrc1[i][koff4]; }
        }
        if (c + 1 < NCH) CP_WAIT1(); else CP_WAIT0();
        __syncthreads();

        const uint32_t* ab = As[buf];
        const uint32_t* bb = Bs[buf];

        uint32_t ah[2][4], al[2][4];
#pragma unroll
        for (int mt = 0; mt < 2; mt++) {
            int r = wm * 32 + mt * 16 + grp;
            int b0 = r * RS, b1 = (r + 8) * RS;
            ah[mt][0] = ab[b0 + tig];     ah[mt][1] = ab[b1 + tig];
            ah[mt][2] = ab[b0 + tig + 4]; ah[mt][3] = ab[b1 + tig + 4];
            al[mt][0] = ab[b0 + 8 + tig];     al[mt][1] = ab[b1 + 8 + tig];
            al[mt][2] = ab[b0 + 8 + tig + 4]; al[mt][3] = ab[b1 + 8 + tig + 4];
        }
        uint32_t bh[4][2], bl[4][2];
#pragma unroll
        for (int nt = 0; nt < 4; nt++) {
            int n = wn * 32 + nt * 8 + grp;
            int nb = n * RS;
            bh[nt][0] = bb[nb + tig]; bh[nt][1] = bb[nb + tig + 4];
            bl[nt][0] = bb[nb + 8 + tig]; bl[nt][1] = bb[nb + 8 + tig + 4];
        }
#pragma unroll
        for (int mt = 0; mt < 2; mt++)
#pragma unroll
            for (int nt = 0; nt < 4; nt++) {
                mma16(acc[mt][nt], ah[mt], bh[nt]);
                mma16(acc[mt][nt], ah[mt], bl[nt]);
                mma16(acc[mt][nt], al[mt], bh[nt]);
            }
        __syncthreads();

        if (c + 2 < NCH) {
            cp16(bdst[buf], bsrc + (c + 2) * 16);
            CP_COMMIT();
        }
    }

    // epilogue
#pragma unroll
    for (int mt = 0; mt < 2; mt++) {
        int r0 = row0 + wm * 32 + mt * 16 + grp;
        int r1 = r0 + 8;
#pragma unroll
        for (int nt = 0; nt < 4; nt++) {
            int coff = c0 + wn * 32 + nt * 8 + tig * 2;
            float2 v0 = make_float2(acc[mt][nt][0], acc[mt][nt][1]);
            float2 v1 = make_float2(acc[mt][nt][2], acc[mt][nt][3]);
            *reinterpret_cast<float2*>(out + (size_t)r0 * DMODEL + coff) = v0;
            *reinterpret_cast<float2*>(out + (size_t)r1 * DMODEL + coff) = v1;
        }
    }
}

// ---------------- load-balancing loss (fp64) ----------------
__global__ void lbloss_kernel(float* __restrict__ out_scalar) {
    if (threadIdx.x == 0 && blockIdx.x == 0) {
        double lb = 0.0;
#pragma unroll
        for (int e = 0; e < NEXP; e++) {
            double m = g_esum[e] / (double)NTOK;
            lb += m * log(m * (double)NEXP + 1e-10);
        }
        out_scalar[0] = (float)((double)NEXP * lb);
    }
}

// ---------------- launch ----------------
extern "C" void kernel_launch(void* const* d_in, const int* in_sizes, int n_in,
                              void* d_out, int out_size) {
    const float* x        = (const float*)d_in[0];
    const float* w_router = (const float*)d_in[1];
    const float* w_gate   = (const float*)d_in[2];
    const float* w_up     = (const float*)d_in[3];
    const float* w_down   = (const float*)d_in[4];
    float* out = (float*)d_out;

    zero_small_kernel<<<1, 32>>>();
    prep_xc<<<(NTOK * DMODEL / 4) / 256, 256>>>(x);
    prep_wgu<<<dim3(EHDIM / 32, DMODEL / 32), dim3(32, 8)>>>(w_gate, w_up);
    prep_wd<<<dim3(DMODEL / 32, HDIM / 32), dim3(32, 8)>>>(w_down);
    router_kernel<<<NTOK / 8, 256>>>(x, w_router);

    gateup_mma<<<dim3(NTOK / 128, HDIM / 64, NEXP), 256>>>();
    down_mma<<<dim3(NTOK / 128, DMODEL / 64), 256>>>(out);

    lbloss_kernel<<<1, 32>>>(out + (out_size - 1));
}

// round 6
// speedup vs baseline: 2.2305x; 1.0105x over previous
#include <cuda_runtime.h>
#include <cuda_bf16.h>
#include <math.h>
#include <stdint.h>

#define NTOK 4096
#define DMODEL 512
#define NEXP 8
#define HDIM 2048
#define EHDIM (NEXP * HDIM)   // 16384

// ---------------- device scratch ----------------
__device__ __align__(16) unsigned short g_xh[NTOK * DMODEL];
__device__ __align__(16) unsigned short g_xl[NTOK * DMODEL];
__device__ __align__(16) unsigned short g_wgh[EHDIM * DMODEL];
__device__ __align__(16) unsigned short g_wgl[EHDIM * DMODEL];
__device__ __align__(16) unsigned short g_wuh[EHDIM * DMODEL];
__device__ __align__(16) unsigned short g_wul[EHDIM * DMODEL];
__device__ __align__(16) unsigned short g_wdh[DMODEL * HDIM];
__device__ __align__(16) unsigned short g_wdl[DMODEL * HDIM];
__device__ __align__(16) float  g_part[2 * NTOK * HDIM];
__device__ int    g_cnt[NEXP];
__device__ double g_esum[NEXP];
__device__ int    g_elist[NEXP * NTOK];   // token | (slot<<16)
__device__ float  g_eprob[NEXP * NTOK];

// ---------------- helpers ----------------
__device__ __forceinline__ uint32_t smem_u32(const void* p) {
    uint32_t a;
    asm("{ .reg .u64 t; cvta.to.shared.u64 t, %1; cvt.u32.u64 %0, t; }"
        : "=r"(a) : "l"(p));
    return a;
}
__device__ __forceinline__ void cp16(uint32_t dst, const void* src) {
    asm volatile("cp.async.cg.shared.global [%0], [%1], 16;" :: "r"(dst), "l"(src));
}
#define CP_COMMIT() asm volatile("cp.async.commit_group;" ::: "memory")
#define CP_WAIT2()  asm volatile("cp.async.wait_group 2;" ::: "memory")
#define CP_WAIT1()  asm volatile("cp.async.wait_group 1;" ::: "memory")
#define CP_WAIT0()  asm volatile("cp.async.wait_group 0;" ::: "memory")

__device__ __forceinline__ void ldm4(uint32_t* r, uint32_t addr) {
    asm volatile("ldmatrix.sync.aligned.m8n8.x4.shared.b16 {%0,%1,%2,%3}, [%4];"
                 : "=r"(r[0]), "=r"(r[1]), "=r"(r[2]), "=r"(r[3]) : "r"(addr));
}

// m16n8k16 bf16 MMA (sm_80 baseline PTX -> tensor pipe)
__device__ __forceinline__ void mma16(float* c, const uint32_t* a, const uint32_t* b) {
    asm volatile(
        "mma.sync.aligned.m16n8k16.row.col.f32.bf16.bf16.f32 "
        "{%0,%1,%2,%3}, {%4,%5,%6,%7}, {%8,%9}, {%0,%1,%2,%3};"
        : "+f"(c[0]), "+f"(c[1]), "+f"(c[2]), "+f"(c[3])
        : "r"(a[0]), "r"(a[1]), "r"(a[2]), "r"(a[3]), "r"(b[0]), "r"(b[1]));
}

__device__ __forceinline__ void bsplit(float v, unsigned short& h, unsigned short& l) {
    __nv_bfloat16 hb = __float2bfloat16(v);
    h = __bfloat16_as_ushort(hb);
    float r = v - __bfloat162float(hb);
    l = __bfloat16_as_ushort(__float2bfloat16(r));
}
__device__ __forceinline__ uint32_t pack2(unsigned short a, unsigned short b) {
    return (uint32_t)a | ((uint32_t)b << 16);
}

// ---------------- prep kernels ----------------
__global__ void zero_small_kernel() {
    int t = threadIdx.x;
    if (t < NEXP) { g_cnt[t] = 0; g_esum[t] = 0.0; }
}

__global__ void prep_xc(const float* __restrict__ x) {
    int i = blockIdx.x * blockDim.x + threadIdx.x;
    float4 v = reinterpret_cast<const float4*>(x)[i];
    unsigned short h0, h1, h2, h3, l0, l1, l2, l3;
    bsplit(v.x, h0, l0); bsplit(v.y, h1, l1);
    bsplit(v.z, h2, l2); bsplit(v.w, h3, l3);
    reinterpret_cast<ushort4*>(g_xh)[i] = make_ushort4(h0, h1, h2, h3);
    reinterpret_cast<ushort4*>(g_xl)[i] = make_ushort4(l0, l1, l2, l3);
}

__global__ void prep_wgu(const float* __restrict__ wg, const float* __restrict__ wu) {
    __shared__ float tg[32][33], tu[32][33];
    int hb = blockIdx.x * 32, db = blockIdx.y * 32;
    int tx = threadIdx.x, ty = threadIdx.y;   // (32, 8)
#pragma unroll
    for (int i = 0; i < 4; i++) {
        int d = db + ty + i * 8;
        tg[ty + i * 8][tx] = wg[(size_t)d * EHDIM + hb + tx];
        tu[ty + i * 8][tx] = wu[(size_t)d * EHDIM + hb + tx];
    }
    __syncthreads();
#pragma unroll
    for (int i = 0; i < 4; i++) {
        int h = hb + ty + i * 8;
        size_t o = (size_t)h * DMODEL + db + tx;
        unsigned short hh, ll;
        bsplit(tg[tx][ty + i * 8], hh, ll);
        g_wgh[o] = hh; g_wgl[o] = ll;
        bsplit(tu[tx][ty + i * 8], hh, ll);
        g_wuh[o] = hh; g_wul[o] = ll;
    }
}

__global__ void prep_wd(const float* __restrict__ wd) {
    __shared__ float t[32][33];
    int db = blockIdx.x * 32, hb = blockIdx.y * 32;
    int tx = threadIdx.x, ty = threadIdx.y;
#pragma unroll
    for (int i = 0; i < 4; i++) {
        t[ty + i * 8][tx] = wd[(size_t)(hb + ty + i * 8) * DMODEL + db + tx];
    }
    __syncthreads();
#pragma unroll
    for (int i = 0; i < 4; i++) {
        size_t o = (size_t)(db + ty + i * 8) * HDIM + hb + tx;
        unsigned short hh, ll;
        bsplit(t[tx][ty + i * 8], hh, ll);
        g_wdh[o] = hh; g_wdl[o] = ll;
    }
}

// ---------------- router: one warp per token ----------------
__global__ void router_kernel(const float* __restrict__ x,
                              const float* __restrict__ w_router) {
    int warp = (blockIdx.x * blockDim.x + threadIdx.x) >> 5;
    int lane = threadIdx.x & 31;
    if (warp >= NTOK) return;
    int n = warp;

    float acc[NEXP];
#pragma unroll
    for (int e = 0; e < NEXP; e++) acc[e] = 0.f;
    const float* xr = x + (size_t)n * DMODEL;
    for (int d = lane; d < DMODEL; d += 32) {
        float xv = xr[d];
        const float* w = w_router + d * NEXP;
#pragma unroll
        for (int e = 0; e < NEXP; e++) acc[e] += xv * w[e];
    }
#pragma unroll
    for (int off = 16; off > 0; off >>= 1)
#pragma unroll
        for (int e = 0; e < NEXP; e++)
            acc[e] += __shfl_xor_sync(0xFFFFFFFFu, acc[e], off);

    if (lane == 0) {
        float mx = acc[0];
#pragma unroll
        for (int e = 1; e < NEXP; e++) mx = fmaxf(mx, acc[e]);
        float s = 0.f, probs[NEXP];
#pragma unroll
        for (int e = 0; e < NEXP; e++) { probs[e] = expf(acc[e] - mx); s += probs[e]; }
        float inv = 1.f / s;
#pragma unroll
        for (int e = 0; e < NEXP; e++) {
            probs[e] *= inv;
            atomicAdd(&g_esum[e], (double)probs[e]);
        }
        int i1 = 0;
#pragma unroll
        for (int e = 1; e < NEXP; e++) if (probs[e] > probs[i1]) i1 = e;
        int i2 = (i1 == 0) ? 1 : 0;
#pragma unroll
        for (int e = 0; e < NEXP; e++)
            if (e != i1 && probs[e] > probs[i2]) i2 = e;

        float p1 = probs[i1], p2 = probs[i2];
        float rn = 1.f / (p1 + p2 + 1e-10f);
        int pos1 = atomicAdd(&g_cnt[i1], 1);
        g_elist[i1 * NTOK + pos1] = n;                // slot 0
        g_eprob[i1 * NTOK + pos1] = p1 * rn;
        int pos2 = atomicAdd(&g_cnt[i2], 1);
        g_elist[i2 * NTOK + pos2] = n | (1 << 16);    // slot 1
        g_eprob[i2 * NTOK + pos2] = p2 * rn;
    }
}

// ---------------- gate/up split-bf16 warp-MMA GEMM ----------------
// 512 threads = 16 warps (wm 0..3 x wn 0..3). BM=128 tokens, BN=64 h (G and U).
// smem row = [hi 8 words | lo 8 words | pad 4] stride 20 words (80B). 3-stage.
#define RS 20
#define XSTG 10240          // 128*RS*4
#define WSTG 5120           // 64*RS*4
#define GU_X(s)  ((s) * XSTG)
#define GU_G(s)  (3 * XSTG + (s) * WSTG)
#define GU_U(s)  (3 * XSTG + 3 * WSTG + (s) * WSTG)
#define GU_META  (3 * XSTG + 6 * WSTG)
#define GU_DYN   (GU_META + 1536)

__global__ __launch_bounds__(512, 1) void gateup_mma() {
    extern __shared__ __align__(16) char smem[];
    uint32_t sb = smem_u32(smem);
    float*  sP   = reinterpret_cast<float*>(smem + GU_META);
    float** sDst = reinterpret_cast<float**>(smem + GU_META + 512);

    const int tid = threadIdx.x;
    const int e = blockIdx.z;
    const int cnt = g_cnt[e];
    const int row0 = blockIdx.x * 128;
    if (row0 >= cnt) return;
    const int h0 = blockIdx.y * 64;

    if (tid < 128) {
        int gr = row0 + tid;
        bool valid = gr < cnt;
        int ent = valid ? g_elist[e * NTOK + gr] : 0;
        int t = ent & 0xFFFF;
        int slot = (ent >> 16) & 1;
        sP[tid] = valid ? g_eprob[e * NTOK + gr] : 0.f;
        sDst[tid] = valid ? (g_part + ((size_t)slot * NTOK + t) * HDIM + h0) : (float*)0;
    }

    // cp.async: X -> 1 op/thread (128 rows x 4 segs). W -> tid<256 G, else U.
    const int q = tid & 3, hilo = q >> 1, seg = q & 1;
    const int xr = tid >> 2;                 // 0..127
    const unsigned short* xsrc;
    {
        int gr = row0 + xr;
        int ent = (gr < cnt) ? g_elist[e * NTOK + gr] : 0;
        int t = ent & 0xFFFF;
        xsrc = (hilo ? g_xl : g_xh) + (size_t)t * DMODEL + seg * 8;
    }
    const uint32_t xoff = (uint32_t)xr * 80 + hilo * 32 + seg * 16;

    const int wrow = (tid & 255) >> 2;       // 0..63
    const unsigned short* wsrc;
    {
        size_t wro = (size_t)(e * HDIM + h0 + wrow) * DMODEL + seg * 8;
        wsrc = (tid < 256) ? ((hilo ? g_wgl : g_wgh) + wro)
                           : ((hilo ? g_wul : g_wuh) + wro);
    }
    const uint32_t woff = (uint32_t)wrow * 80 + hilo * 32 + seg * 16;
    const uint32_t wreg = (tid < 256) ? 0u : 1u;   // 0 -> G region, 1 -> U region

    // fragment (ldmatrix) addressing
    const int warp = tid >> 5, lane = tid & 31;
    const int wm = warp & 3, wn = warp >> 2;
    const int grp = lane >> 2, tig = lane & 3;
    const uint32_t aLane = (uint32_t)(((lane & 7) + (lane & 8)) * 80 + ((lane & 16) ? 16 : 0));
    const uint32_t bLane = (uint32_t)((((lane & 7) + ((lane & 16) >> 1)) * 80) + ((lane & 8) ? 16 : 0));
    uint32_t aB[2][2];   // [mt][hilo]
#pragma unroll
    for (int mt = 0; mt < 2; mt++)
#pragma unroll
        for (int hl = 0; hl < 2; hl++)
            aB[mt][hl] = (uint32_t)((wm * 32 + mt * 16) * 80 + hl * 32) + aLane;
    uint32_t bB[2] = { (uint32_t)(wn * 16 * 80) + bLane,
                       (uint32_t)(wn * 16 * 80 + 32) + bLane };

    float accG[2][2][4], accU[2][2][4];
#pragma unroll
    for (int mt = 0; mt < 2; mt++)
#pragma unroll
        for (int nt = 0; nt < 2; nt++)
#pragma unroll
            for (int k = 0; k < 4; k++) { accG[mt][nt][k] = 0.f; accU[mt][nt][k] = 0.f; }

    // prologue: stages 0..2
#pragma unroll
    for (int c = 0; c < 3; c++) {
        cp16(sb + GU_X(c) + xoff, xsrc + c * 16);
        cp16(sb + (wreg ? GU_U(c) : GU_G(c)) + woff, wsrc + c * 16);
        CP_COMMIT();
    }

    const int NCH = DMODEL / 16;   // 32
    for (int c = 0; c < NCH; c++) {
        int s = c % 3;
        if (c < NCH - 2) CP_WAIT2(); else if (c == NCH - 2) CP_WAIT1(); else CP_WAIT0();
        __syncthreads();

        uint32_t xbase = sb + GU_X(s);
        uint32_t gbase = sb + GU_G(s);
        uint32_t ubase = sb + GU_U(s);

        uint32_t ah[2][4], al[2][4];
        ldm4(ah[0], xbase + aB[0][0]); ldm4(al[0], xbase + aB[0][1]);
        ldm4(ah[1], xbase + aB[1][0]); ldm4(al[1], xbase + aB[1][1]);
        uint32_t gH[4], gL[4], uH[4], uL[4];
        ldm4(gH, gbase + bB[0]); ldm4(gL, gbase + bB[1]);
        ldm4(uH, ubase + bB[0]); ldm4(uL, ubase + bB[1]);

#pragma unroll
        for (int mt = 0; mt < 2; mt++)
#pragma unroll
            for (int nt = 0; nt < 2; nt++) {
                mma16(accG[mt][nt], ah[mt], gH + nt * 2);
                mma16(accU[mt][nt], ah[mt], uH + nt * 2);
                mma16(accG[mt][nt], ah[mt], gL + nt * 2);
                mma16(accU[mt][nt], ah[mt], uL + nt * 2);
                mma16(accG[mt][nt], al[mt], gH + nt * 2);
                mma16(accU[mt][nt], al[mt], uH + nt * 2);
            }
        __syncthreads();

        if (c + 3 < NCH) {
            int k0 = (c + 3) * 16;
            cp16(sb + GU_X(s) + xoff, xsrc + k0);
            cp16(sb + (wreg ? GU_U(s) : GU_G(s)) + woff, wsrc + k0);
            CP_COMMIT();
        }
    }

    // epilogue: p * silu(g) * u, one exact store per (token,slot,h)
#pragma unroll
    for (int mt = 0; mt < 2; mt++) {
        int r0 = wm * 32 + mt * 16 + grp;
        int r1 = r0 + 8;
        float p0 = sP[r0], p1 = sP[r1];
        float* d0 = sDst[r0];
        float* d1 = sDst[r1];
#pragma unroll
        for (int nt = 0; nt < 2; nt++) {
            int coff = wn * 16 + nt * 8 + tig * 2;
            if (d0) {
                float g0 = accG[mt][nt][0], u0 = accU[mt][nt][0];
                float g1 = accG[mt][nt][1], u1 = accU[mt][nt][1];
                float2 v;
                v.x = p0 * (g0 / (1.f + __expf(-g0))) * u0;
                v.y = p0 * (g1 / (1.f + __expf(-g1))) * u1;
                *reinterpret_cast<float2*>(d0 + coff) = v;
            }
            if (d1) {
                float g2 = accG[mt][nt][2], u2 = accU[mt][nt][2];
                float g3 = accG[mt][nt][3], u3 = accU[mt][nt][3];
                float2 v;
                v.x = p1 * (g2 / (1.f + __expf(-g2))) * u2;
                v.y = p1 * (g3 / (1.f + __expf(-g3))) * u3;
                *reinterpret_cast<float2*>(d1 + coff) = v;
            }
        }
    }
}

// ---------------- down split-bf16 warp-MMA GEMM ----------------
// 512 threads, BM=128, BN=64, K=2048 in chunks of 16. A summed+split in regs.
__global__ __launch_bounds__(512, 1) void down_mma(float* __restrict__ out) {
    __shared__ __align__(16) uint32_t As[3][128 * RS];
    __shared__ __align__(16) uint32_t Bs[3][64 * RS];

    const int tid = threadIdx.x;
    const int row0 = blockIdx.x * 128;
    const int c0 = blockIdx.y * 64;

    // A staging: 1 float4 per thread per chunk (128 rows x 4 float4)
    const int ar = tid >> 2, ac4 = tid & 3;
    const float4* asrc0 =
        reinterpret_cast<const float4*>(g_part + (size_t)(row0 + ar) * HDIM) + ac4;
    const float4* asrc1 =
        reinterpret_cast<const float4*>(g_part + (size_t)NTOK * HDIM +
                                        (size_t)(row0 + ar) * HDIM) + ac4;
    uint32_t adh0 = smem_u32(&As[0][ar * RS + ac4 * 2]);

    // B: tid<256, 64 rows x 4 segs
    const int q = tid & 3, hilo = q >> 1, seg = q & 1;
    const int brow = tid >> 2;   // valid when tid<256
    const unsigned short* bsrc =
        (hilo ? g_wdl : g_wdh) + (size_t)(c0 + (brow & 63)) * HDIM + seg * 8;
    uint32_t boff = (uint32_t)(brow & 63) * 80 + hilo * 32 + seg * 16;
    uint32_t b0addr = smem_u32(&Bs[0][0]) + boff;

    const int warp = tid >> 5, lane = tid & 31;
    const int wm = warp & 3, wn = warp >> 2;
    const int grp = lane >> 2, tig = lane & 3;
    const uint32_t aLane = (uint32_t)(((lane & 7) + (lane & 8)) * 80 + ((lane & 16) ? 16 : 0));
    const uint32_t bLane = (uint32_t)((((lane & 7) + ((lane & 16) >> 1)) * 80) + ((lane & 8) ? 16 : 0));
    uint32_t aFB[2][2];
#pragma unroll
    for (int mt = 0; mt < 2; mt++)
#pragma unroll
        for (int hl = 0; hl < 2; hl++)
            aFB[mt][hl] = smem_u32(&As[0][0]) + (uint32_t)((wm * 32 + mt * 16) * 80 + hl * 32) + aLane;
    uint32_t bFB[2] = { smem_u32(&Bs[0][0]) + (uint32_t)(wn * 16 * 80) + bLane,
                        smem_u32(&Bs[0][0]) + (uint32_t)(wn * 16 * 80 + 32) + bLane };

    float acc[2][2][4];
#pragma unroll
    for (int mt = 0; mt < 2; mt++)
#pragma unroll
        for (int nt = 0; nt < 2; nt++)
#pragma unroll
            for (int k = 0; k < 4; k++) acc[mt][nt][k] = 0.f;

    float4 rA0 = asrc0[0], rA1 = asrc1[0];

#pragma unroll
    for (int c = 0; c < 3; c++) {
        if (tid < 256) cp16(b0addr + c * WSTG, bsrc + c * 16);
        CP_COMMIT();
    }

    const int NCH = HDIM / 16;   // 128
    for (int c = 0; c < NCH; c++) {
        int s = c % 3;
        // store A chunk c (sum + bf16 split) into stage s
        {
            float s0 = rA0.x + rA1.x, s1 = rA0.y + rA1.y;
            float s2 = rA0.z + rA1.z, s3 = rA0.w + rA1.w;
            unsigned short h0, h1, h2, h3, l0, l1, l2, l3;
            bsplit(s0, h0, l0); bsplit(s1, h1, l1);
            bsplit(s2, h2, l2); bsplit(s3, h3, l3);
            uint32_t hw0 = pack2(h0, h1), hw1 = pack2(h2, h3);
            uint32_t lw0 = pack2(l0, l1), lw1 = pack2(l2, l3);
            uint32_t dst = adh0 + s * XSTG;
            asm volatile("st.shared.v2.b32 [%0], {%1,%2};"
                         :: "r"(dst), "r"(hw0), "r"(hw1) : "memory");
            asm volatile("st.shared.v2.b32 [%0], {%1,%2};"
                         :: "r"(dst + 32), "r"(lw0), "r"(lw1) : "memory");
        }
        if (c + 1 < NCH) { rA0 = asrc0[(c + 1) * 4]; rA1 = asrc1[(c + 1) * 4]; }
        if (c < NCH - 2) CP_WAIT2(); else if (c == NCH - 2) CP_WAIT1(); else CP_WAIT0();
        __syncthreads();

        uint32_t ah[2][4], al[2][4];
        ldm4(ah[0], aFB[0][0] + s * XSTG); ldm4(al[0], aFB[0][1] + s * XSTG);
        ldm4(ah[1], aFB[1][0] + s * XSTG); ldm4(al[1], aFB[1][1] + s * XSTG);
        uint32_t bH[4], bL[4];
        ldm4(bH, bFB[0] + s * WSTG); ldm4(bL, bFB[1] + s * WSTG);

#pragma unroll
        for (int mt = 0; mt < 2; mt++)
#pragma unroll
            for (int nt = 0; nt < 2; nt++) {
                mma16(acc[mt][nt], ah[mt], bH + nt * 2);
                mma16(acc[mt][nt], ah[mt], bL + nt * 2);
                mma16(acc[mt][nt], al[mt], bH + nt * 2);
            }
        __syncthreads();

        if (c + 3 < NCH) {
            if (tid < 256) cp16(b0addr + s * WSTG, bsrc + (c + 3) * 16);
            CP_COMMIT();
        }
    }

    // epilogue
#pragma unroll
    for (int mt = 0; mt < 2; mt++) {
        int r0 = row0 + wm * 32 + mt * 16 + grp;
        int r1 = r0 + 8;
#pragma unroll
        for (int nt = 0; nt < 2; nt++) {
            int coff = c0 + wn * 16 + nt * 8 + tig * 2;
            float2 v0 = make_float2(acc[mt][nt][0], acc[mt][nt][1]);
            float2 v1 = make_float2(acc[mt][nt][2], acc[mt][nt][3]);
            *reinterpret_cast<float2*>(out + (size_t)r0 * DMODEL + coff) = v0;
            *reinterpret_cast<float2*>(out + (size_t)r1 * DMODEL + coff) = v1;
        }
    }
}

// ---------------- load-balancing loss (fp64) ----------------
__global__ void lbloss_kernel(float* __restrict__ out_scalar) {
    if (threadIdx.x == 0 && blockIdx.x == 0) {
        double lb = 0.0;
#pragma unroll
        for (int e = 0; e < NEXP; e++) {
            double m = g_esum[e] / (double)NTOK;
            lb += m * log(m * (double)NEXP + 1e-10);
        }
        out_scalar[0] = (float)((double)NEXP * lb);
    }
}

// ---------------- launch ----------------
extern "C" void kernel_launch(void* const* d_in, const int* in_sizes, int n_in,
                              void* d_out, int out_size) {
    const float* x        = (const float*)d_in[0];
    const float* w_router = (const float*)d_in[1];
    const float* w_gate   = (const float*)d_in[2];
    const float* w_up     = (const float*)d_in[3];
    const float* w_down   = (const float*)d_in[4];
    float* out = (float*)d_out;

    cudaFuncSetAttribute(gateup_mma, cudaFuncAttributeMaxDynamicSharedMemorySize, GU_DYN);

    zero_small_kernel<<<1, 32>>>();
    prep_xc<<<(NTOK * DMODEL / 4) / 256, 256>>>(x);
    prep_wgu<<<dim3(EHDIM / 32, DMODEL / 32), dim3(32, 8)>>>(w_gate, w_up);
    prep_wd<<<dim3(DMODEL / 32, HDIM / 32), dim3(32, 8)>>>(w_down);
    router_kernel<<<NTOK / 8, 256>>>(x, w_router);

    gateup_mma<<<dim3(NTOK / 128, HDIM / 64, NEXP), 512, GU_DYN>>>();
    down_mma<<<dim3(NTOK / 128, DMODEL / 64), 512>>>(out);

    lbloss_kernel<<<1, 32>>>(out + (out_size - 1));
}